// round 15
// baseline (speedup 1.0000x reference)
#include <cuda_runtime.h>
#include <cuda_fp16.h>
#include <cstdint>

// ===========================================================================
// AttnBlock via mma.sync m16n8k16 fp16 (fp32 accum), sm_100-safe.
// Round 15: R14 base + 3-stage cp.async pipeline with prefetch distance 2
// (CP_WAIT(1)) — compute never drains the most-recent copy group.
// smem 110.6KB/CTA, still 2 CTAs/SM (221KB <= 228KB).
// ===========================================================================

namespace {
constexpr int CH   = 512;
constexpr int NB   = 4;
constexpr int HWs  = 4096;
constexpr int PWs  = 66;
constexpr int PHWs = PWs * PWs;   // 4356

constexpr int BM = 128, BN = 128, BK = 64;
constexpr int RS = 72;                           // padded row stride (halfs)
constexpr int A_HALFS = BM * RS;                 // 9216
constexpr int A_BYTES = A_HALFS * 2;             // 18432
constexpr int STAGE_BYTES = 2 * A_BYTES;         // 36864
constexpr int SMEM_DYN = 3 * STAGE_BYTES;        // 110592
constexpr int SMEM_LN  = CH * 33 * 4;            // 67584
}

// ------------------------- scratch (device globals) ------------------------
__device__ float  g_inv[NB * HWs];                 // 1/rowsum of exp
__device__ float  g_pmx[(size_t)NB * HWs * 64];    // per-row 64-col max partials
__device__ __half g_hpT[(size_t)NB * PHWs * CH];   // padded LN out, channel-last
__device__ __half g_qT [(size_t)NB * HWs * CH];    // [p][c]
__device__ __half g_kT [(size_t)NB * HWs * CH];    // [p][c]
__device__ __half g_v  [(size_t)NB * CH * HWs];    // [c][p]
__device__ __half g_aoT[(size_t)NB * HWs * CH];    // [p][c]
__device__ __half g_SP [(size_t)NB * HWs * HWs];   // fp16 logits -> unnorm probs
__device__ __half g_wkt[(size_t)9 * CH * CH];      // [t][o][i] fp16
__device__ __half g_wvt[(size_t)9 * CH * CH];
__device__ __half g_wqh[(size_t)CH * CH];
__device__ __half g_wph[(size_t)CH * CH];

// ------------------------------ PTX helpers --------------------------------
#define CP16(sa, g) \
    asm volatile("cp.async.cg.shared.global [%0], [%1], 16;" :: "r"(sa), "l"(g))
#define CP16CA(sa, g) \
    asm volatile("cp.async.ca.shared.global [%0], [%1], 16;" :: "r"(sa), "l"(g))
#define CP_COMMIT() asm volatile("cp.async.commit_group;" ::: "memory")
#define CP_WAIT(n)  asm volatile("cp.async.wait_group %0;" :: "n"(n) : "memory")

__device__ __forceinline__ uint32_t smem_u32(const void* p) {
    uint32_t a;
    asm("{ .reg .u64 t; cvta.to.shared.u64 t, %1; cvt.u32.u64 %0, t; }"
        : "=r"(a) : "l"(p));
    return a;
}

#define MMA_F16(c, a, b) \
    asm volatile("mma.sync.aligned.m16n8k16.row.col.f32.f16.f16.f32 " \
        "{%0,%1,%2,%3}, {%4,%5,%6,%7}, {%8,%9}, {%0,%1,%2,%3};" \
        : "+f"((c)[0]), "+f"((c)[1]), "+f"((c)[2]), "+f"((c)[3]) \
        : "r"((a)[0]), "r"((a)[1]), "r"((a)[2]), "r"((a)[3]), \
          "r"((b)[0]), "r"((b)[1]))

#define LDSM_X4(r0, r1, r2, r3, addr) \
    asm volatile("ldmatrix.sync.aligned.m8n8.x4.shared.b16 {%0,%1,%2,%3}, [%4];" \
        : "=r"(r0), "=r"(r1), "=r"(r2), "=r"(r3) : "r"(addr))

// FMA-pipe exp (no MUFU): exp(x) = 2^n * e^t, |t| <= ln2/2.  rel err ~2.4e-6.
__device__ __forceinline__ float fexp(float x) {
    x = fmaxf(x, -80.f);
    float y  = x * 1.4426950408889634f;
    float fn = rintf(y);
    float t  = (y - fn) * 0.6931471805599453f;
    float p  = 8.3333333e-3f;
    p = fmaf(p, t, 4.1666667e-2f);
    p = fmaf(p, t, 1.6666667e-1f);
    p = fmaf(p, t, 0.5f);
    p = fmaf(p, t, 1.f);
    p = fmaf(p, t, 1.f);
    return p * __int_as_float(((int)fn + 127) << 23);
}

// ------------------------------- small kernels ------------------------------
// weight prep (blocks 0..1023) + hpT border zero (blocks 1024..1039)
__global__ void k_prep(const float* __restrict__ wq, const float* __restrict__ wk,
                       const float* __restrict__ wv, const float* __restrict__ wp) {
    if (blockIdx.x < 1024) {
        int g = blockIdx.x * 256 + threadIdx.x;
        g_wqh[g] = __float2half(wq[g]);
        g_wph[g] = __float2half(wp[g]);
        #pragma unroll
        for (int t = 0; t < 9; t++) {
            g_wkt[(size_t)t * CH * CH + g] = __float2half(wk[(size_t)g * 9 + t]);
            g_wvt[(size_t)t * CH * CH + g] = __float2half(wv[(size_t)g * 9 + t]);
        }
    } else {
        const int jb = blockIdx.x - 1024;          // 0..15
        for (int r = 0; r < 65; r++) {
            int j = jb * 65 + r;                   // 0..1039
            int b = j / 260, i = j % 260;
            int spo;
            if (i < 66)       spo = i;                      // row 0
            else if (i < 132) spo = 65 * PWs + (i - 66);    // row 65
            else if (i < 196) spo = (i - 131) * PWs;        // col 0
            else              spo = (i - 195) * PWs + 65;   // col 65
            ((uint32_t*)&g_hpT[((size_t)b * PHWs + spo) * CH])[threadIdx.x] = 0u;
        }
    }
}

// fused LayerNorm: one x read, stats in-tile, transposed fp16 write to hpT
__global__ void k_ln_fused(const float* __restrict__ x,
                           const float* __restrict__ lw,
                           const float* __restrict__ lb) {
    extern __shared__ float tile[];            // [CH][33]
    __shared__ float rs1[8][32], rs2[8][32];
    const int b = blockIdx.y;
    const int p0 = blockIdx.x * 32;
    const int lx = threadIdx.x & 31, ly = threadIdx.x >> 5;

    const float* xb = x + (size_t)b * CH * HWs + p0;
    float s = 0.f, s2 = 0.f;
    for (int c = ly; c < CH; c += 8) {
        float v = xb[(size_t)c * HWs + lx];
        tile[c * 33 + lx] = v;
        s += v; s2 += v * v;
    }
    rs1[ly][lx] = s; rs2[ly][lx] = s2;
    __syncthreads();
    if (ly == 0) {
        float a = 0.f, a2 = 0.f;
        #pragma unroll
        for (int j = 0; j < 8; j++) { a += rs1[j][lx]; a2 += rs2[j][lx]; }
        float mu = a * (1.f / CH);
        float var = a2 * (1.f / CH) - mu * mu;
        rs1[0][lx] = mu;
        rs2[0][lx] = rsqrtf(var + 1e-6f);
    }
    __syncthreads();

    const int c2 = threadIdx.x * 2;
    const float w0 = lw[c2], w1 = lw[c2 + 1];
    const float b0 = lb[c2], b1 = lb[c2 + 1];
    #pragma unroll 4
    for (int pp = 0; pp < 32; pp++) {
        const float mu = rs1[0][pp], r = rs2[0][pp];
        float v0 = (tile[c2 * 33 + pp] - mu) * r * w0 + b0;
        float v1 = (tile[(c2 + 1) * 33 + pp] - mu) * r * w1 + b1;
        int p = p0 + pp;
        int spo = ((p >> 6) + 1) * PWs + (p & 63) + 1;
        *(__half2*)&g_hpT[((size_t)b * PHWs + spo) * CH + c2] =
            __floats2half2_rn(v0, v1);
    }
}

// single-pass softmax, IN PLACE, 2 rows per block.  Row max from g_pmx.
// Writes UNNORMALIZED exp values; 1/sum goes to g_inv (applied in O-GEMM).
__global__ void k_softmax1(__half* __restrict__ SP) {
    const int b = blockIdx.y;
    __shared__ float red[8];
    const int tid = threadIdx.x;
    const int lane = tid & 31, wid = tid >> 5;

    #pragma unroll
    for (int rr = 0; rr < 2; rr++) {
        const int m = blockIdx.x * 2 + rr;
        __half* row = SP + ((size_t)b * HWs + m) * HWs;
        const float* pm = g_pmx + ((size_t)b * HWs + m) * 64;

        float mx = fmaxf(pm[lane], pm[lane + 32]);
        #pragma unroll
        for (int o = 16; o > 0; o >>= 1)
            mx = fmaxf(mx, __shfl_xor_sync(0xffffffffu, mx, o));

        float ls = 0.f;
        #pragma unroll
        for (int it = 0; it < 2; it++) {
            const int i = tid * 8 + it * 2048;
            uint4 u = *(const uint4*)&row[i];
            __half2* h = (__half2*)&u;
            #pragma unroll
            for (int q = 0; q < 4; q++) {
                float2 f = __half22float2(h[q]);
                f.x = fexp(f.x - mx);
                f.y = fexp(f.y - mx);
                ls += f.x + f.y;
                h[q] = __floats2half2_rn(f.x, f.y);
            }
            *(uint4*)&row[i] = u;
        }
        #pragma unroll
        for (int o = 16; o > 0; o >>= 1)
            ls += __shfl_xor_sync(0xffffffffu, ls, o);
        if (lane == 0) red[wid] = ls;
        __syncthreads();
        if (tid == 0) {
            float sum = 0.f;
            #pragma unroll
            for (int w = 0; w < 8; w++) sum += red[w];
            g_inv[b * HWs + m] = 1.f / sum;
        }
        if (rr == 0) __syncthreads();
    }
}

// ---------------------- fp16 mma.sync GEMM core (templated) -----------------
// Block 128x128, 8 warps of 32x64, BK=64, ST=3 (prefetch distance 2),
// fragment double-buffering.
// MODE 0: dense A(lda) / dense B(ldb)
// MODE 1: A = hpT gather (1 tap), B dense
// MODE 2: A = hpT gather (9 taps), B = weight slabs (+t*CH*CH)
// MODE 3: A = weight slabs,        B = hpT gather (9 taps)
// EPI 0: float C = alpha*acc (+bias[m]) (+resid)
// EPI 2: half  C = alpha*acc * (rowScale ? rowScale[m] : 1)
// EPI 3: half  C = alpha*acc, plus per-row 64-col max -> pmx
template <int MODE, int EPI>
__device__ __forceinline__ void gemm_core(
    const __half* __restrict__ A, const __half* __restrict__ B,
    void* __restrict__ Cv, const float* __restrict__ resid,
    const float* __restrict__ bias, float* __restrict__ pmx,
    const float* __restrict__ rowScale,
    int KT, int lda, int ldb, int ldc,
    float alpha, int mBase, int nBase) {
    extern __shared__ char dsm[];
    const int tid = threadIdx.x;
    const int lane = tid & 31;
    const int w  = tid >> 5;
    const int wm = (w & 3) * 32;
    const int wn = (w >> 2) * 64;
    const int g  = lane >> 2;
    const int t4 = lane & 3;

    // producer addressing: 4 A + 4 B chunks of 16B per thread per k-tile
    uint32_t aSm[4];
    uint32_t aOff[4], bOff[4];
    int q8[4];
    const uint32_t smBase = smem_u32(dsm);
    #pragma unroll
    for (int i = 0; i < 4; i++) {
        int chunk = tid + 256 * i;
        int r = chunk >> 3;
        q8[i] = (chunk & 7) * 8;
        aSm[i] = (uint32_t)(r * RS + q8[i]) * 2u;
        int pa = mBase + r, pb = nBase + r;
        if (MODE == 1 || MODE == 2)
            aOff[i] = (uint32_t)(((pa >> 6) + 1) * PWs + (pa & 63) + 1);
        else
            aOff[i] = (uint32_t)(pa * lda + q8[i]);
        if (MODE == 3)
            bOff[i] = (uint32_t)(((pb >> 6) + 1) * PWs + (pb & 63) + 1);
        else
            bOff[i] = (uint32_t)(pb * ldb + q8[i]);
    }

    // ldmatrix per-lane fragment bases (byte offsets within a stage)
    const uint32_t aFrag = smBase +
        (uint32_t)(((lane & 15) * RS + (lane >> 4) * 8) * 2) + (uint32_t)(wm * RS * 2);
    const uint32_t bFrag = smBase + (uint32_t)A_BYTES +
        (uint32_t)(((((lane & 7) + ((lane >> 4) << 3))) * RS + ((lane >> 3) & 1) * 8) * 2)
        + (uint32_t)(wn * RS * 2);

    float acc[2][8][4];
    #pragma unroll
    for (int mt = 0; mt < 2; mt++)
        #pragma unroll
        for (int nt = 0; nt < 8; nt++)
            #pragma unroll
            for (int e = 0; e < 4; e++) acc[mt][nt][e] = 0.f;

    auto issue = [&](int kt) {
        if (kt < KT) {
            const uint32_t sb = smBase + (uint32_t)((kt % 3) * STAGE_BYTES);
            const int kg = kt * BK;
            if (MODE == 0) {
                #pragma unroll
                for (int i = 0; i < 4; i++) {
                    CP16(sb + aSm[i], A + aOff[i] + kg);
                    CP16(sb + A_BYTES + aSm[i], B + bOff[i] + kg);
                }
            } else {
                int t, kc, off;
                if (MODE == 1) { t = 0; kc = kg; off = 0; }
                else {
                    t = kg >> 9; kc = kg & 511;
                    off = (t / 3 - 1) * PWs + (t % 3 - 1);
                }
                if (MODE == 1 || MODE == 2) {
                    const __half* Slab = B + ((size_t)t << 18);
                    #pragma unroll
                    for (int i = 0; i < 4; i++) {
                        CP16CA(sb + aSm[i],
                               A + ((size_t)(aOff[i] + off) << 9) + kc + q8[i]);
                        CP16(sb + A_BYTES + aSm[i],
                             (MODE == 1) ? (B + bOff[i] + kg) : (Slab + bOff[i] + kc));
                    }
                } else {  // MODE 3
                    const __half* Slab = A + ((size_t)t << 18);
                    #pragma unroll
                    for (int i = 0; i < 4; i++) {
                        CP16(sb + aSm[i], Slab + aOff[i] + kc);
                        CP16CA(sb + A_BYTES + aSm[i],
                               B + ((size_t)(bOff[i] + off) << 9) + kc + q8[i]);
                    }
                }
            }
            CP_COMMIT();
        }
    };

    issue(0);
    issue(1);

    uint32_t a[2][2][4], b[2][8][2];   // double-buffered fragments
    for (int kt = 0; kt < KT; kt++) {
        if (kt + 1 < KT) CP_WAIT(1); else CP_WAIT(0);
        __syncthreads();
        issue(kt + 2);

        const uint32_t soff = (uint32_t)((kt % 3) * STAGE_BYTES);
        // prime fragment buffer 0 (ks = 0)
        LDSM_X4(a[0][0][0], a[0][0][1], a[0][0][2], a[0][0][3], aFrag + soff);
        LDSM_X4(a[0][1][0], a[0][1][1], a[0][1][2], a[0][1][3],
                aFrag + soff + (uint32_t)(16 * RS * 2));
        #pragma unroll
        for (int np = 0; np < 4; np++)
            LDSM_X4(b[0][2 * np][0], b[0][2 * np][1],
                    b[0][2 * np + 1][0], b[0][2 * np + 1][1],
                    bFrag + soff + (uint32_t)(np * 16 * RS * 2));

        #pragma unroll
        for (int ks = 0; ks < 4; ks++) {
            const int cur = ks & 1, nxt = cur ^ 1;
            if (ks < 3) {
                const uint32_t ko2 = soff + (ks + 1) * 32;
                LDSM_X4(a[nxt][0][0], a[nxt][0][1], a[nxt][0][2], a[nxt][0][3],
                        aFrag + ko2);
                LDSM_X4(a[nxt][1][0], a[nxt][1][1], a[nxt][1][2], a[nxt][1][3],
                        aFrag + ko2 + (uint32_t)(16 * RS * 2));
                #pragma unroll
                for (int np = 0; np < 4; np++)
                    LDSM_X4(b[nxt][2 * np][0], b[nxt][2 * np][1],
                            b[nxt][2 * np + 1][0], b[nxt][2 * np + 1][1],
                            bFrag + ko2 + (uint32_t)(np * 16 * RS * 2));
            }
            #pragma unroll
            for (int mt = 0; mt < 2; mt++)
                #pragma unroll
                for (int nt = 0; nt < 8; nt++)
                    MMA_F16(acc[mt][nt], a[cur][mt], b[cur][nt]);
        }
    }

    if (EPI == 0) {
        float* C = (float*)Cv;
        #pragma unroll
        for (int mt = 0; mt < 2; mt++) {
            const int r0 = mBase + wm + mt * 16 + g;
            const int r1 = r0 + 8;
            const float bv0 = bias ? bias[r0] : 0.f;
            const float bv1 = bias ? bias[r1] : 0.f;
            #pragma unroll
            for (int nt = 0; nt < 8; nt++) {
                const int cc = nBase + wn + nt * 8 + 2 * t4;
                float2 o0, o1;
                o0.x = acc[mt][nt][0] * alpha + bv0;
                o0.y = acc[mt][nt][1] * alpha + bv0;
                o1.x = acc[mt][nt][2] * alpha + bv1;
                o1.y = acc[mt][nt][3] * alpha + bv1;
                if (resid) {
                    float2 q0 = *(const float2*)&resid[(size_t)r0 * ldc + cc];
                    float2 q1 = *(const float2*)&resid[(size_t)r1 * ldc + cc];
                    o0.x += q0.x; o0.y += q0.y;
                    o1.x += q1.x; o1.y += q1.y;
                }
                *(float2*)&C[(size_t)r0 * ldc + cc] = o0;
                *(float2*)&C[(size_t)r1 * ldc + cc] = o1;
            }
        }
    } else if (EPI == 2) {
        __half* C = (__half*)Cv;
        #pragma unroll
        for (int mt = 0; mt < 2; mt++) {
            const int r0 = mBase + wm + mt * 16 + g;
            const int r1 = r0 + 8;
            const float s0 = rowScale ? alpha * rowScale[r0] : alpha;
            const float s1 = rowScale ? alpha * rowScale[r1] : alpha;
            #pragma unroll
            for (int nt = 0; nt < 8; nt++) {
                const int cc = nBase + wn + nt * 8 + 2 * t4;
                __half2 h0 = __floats2half2_rn(acc[mt][nt][0] * s0,
                                               acc[mt][nt][1] * s0);
                __half2 h1 = __floats2half2_rn(acc[mt][nt][2] * s1,
                                               acc[mt][nt][3] * s1);
                *(__half2*)&C[(size_t)r0 * ldc + cc] = h0;
                *(__half2*)&C[(size_t)r1 * ldc + cc] = h1;
            }
        }
    } else {  // EPI 3: fp16 store + per-row 64-col max partials
        __half* C = (__half*)Cv;
        const int pblk = (nBase + wn) >> 6;
        #pragma unroll
        for (int mt = 0; mt < 2; mt++) {
            const int r0 = mBase + wm + mt * 16 + g;
            const int r1 = r0 + 8;
            float m0 = -1e30f, m1 = -1e30f;
            #pragma unroll
            for (int nt = 0; nt < 8; nt++) {
                const int cc = nBase + wn + nt * 8 + 2 * t4;
                float a0 = acc[mt][nt][0] * alpha, a1 = acc[mt][nt][1] * alpha;
                float a2 = acc[mt][nt][2] * alpha, a3 = acc[mt][nt][3] * alpha;
                m0 = fmaxf(m0, fmaxf(a0, a1));
                m1 = fmaxf(m1, fmaxf(a2, a3));
                *(__half2*)&C[(size_t)r0 * ldc + cc] = __floats2half2_rn(a0, a1);
                *(__half2*)&C[(size_t)r1 * ldc + cc] = __floats2half2_rn(a2, a3);
            }
            m0 = fmaxf(m0, __shfl_xor_sync(0xffffffffu, m0, 1));
            m0 = fmaxf(m0, __shfl_xor_sync(0xffffffffu, m0, 2));
            m1 = fmaxf(m1, __shfl_xor_sync(0xffffffffu, m1, 1));
            m1 = fmaxf(m1, __shfl_xor_sync(0xffffffffu, m1, 2));
            if (t4 == 0) {
                pmx[(size_t)r0 * 64 + pblk] = m0;
                pmx[(size_t)r1 * 64 + pblk] = m1;
            }
        }
    }
}

// generic GEMM wrapper (S, O, proj) — templated
template <int MODE, int EPI>
__global__ void __launch_bounds__(256, 2)
tgemm(const __half* __restrict__ A, const __half* __restrict__ B,
      void* __restrict__ Cv, const float* __restrict__ resid,
      const float* __restrict__ bias, float* __restrict__ pmx,
      const float* __restrict__ rowScale,
      int KT, int lda, int ldb, int ldc,
      size_t sA, size_t sB, size_t sC, float alpha) {
    const int z = blockIdx.z;
    gemm_core<MODE, EPI>(A + z * sA, B + z * sB,
              (EPI == 0) ? (void*)((float*)Cv + z * sC)
                         : (void*)((__half*)Cv + z * sC),
              resid ? resid + z * sC : nullptr, bias,
              pmx ? pmx + (size_t)z * HWs * 64 : nullptr,
              rowScale ? rowScale + (size_t)z * HWs : nullptr,
              KT, lda, ldb, ldc, alpha,
              blockIdx.y * BM, blockIdx.x * BN);
}

// fused q/k/v conv launch: 384 blocks per batch; heavy v/k first, cheap q last
__global__ void __launch_bounds__(256, 2)
qkv_gemm() {
    const int z = blockIdx.z;
    const size_t sHP = (size_t)PHWs * CH;
    const size_t sPC = (size_t)HWs * CH;
    const __half* hp = g_hpT + z * sHP;
    const int bx = blockIdx.x;
    if (bx < 128) {            // v: M=c, N=p, 9 taps
        gemm_core<3, 2>(g_wvt, hp, g_v + z * sPC, nullptr, nullptr, nullptr, nullptr,
                  72, CH, CH, HWs, 1.f, (bx >> 5) * BM, (bx & 31) * BN);
    } else if (bx < 256) {     // k: M=p, N=c, 9 taps
        const int j = bx - 128;
        gemm_core<2, 2>(hp, g_wkt, g_kT + z * sPC, nullptr, nullptr, nullptr, nullptr,
                  72, CH, CH, CH, 1.f, (j >> 2) * BM, (j & 3) * BN);
    } else {                   // q: M=p, N=c, 1 tap (cheap tail filler)
        const int j = bx - 256;
        gemm_core<1, 2>(hp, g_wqh, g_qT + z * sPC, nullptr, nullptr, nullptr, nullptr,
                  8, CH, CH, CH, 1.f, (j >> 2) * BM, (j & 3) * BN);
    }
}

// ------------------------------- launcher -----------------------------------
extern "C" void kernel_launch(void* const* d_in, const int* in_sizes, int n_in,
                              void* d_out, int out_size) {
    const float* x   = (const float*)d_in[0];
    const float* lnw = (const float*)d_in[1];
    const float* lnb = (const float*)d_in[2];
    const float* wq  = (const float*)d_in[3];
    const float* wk  = (const float*)d_in[4];
    const float* wv  = (const float*)d_in[5];
    const float* wp  = (const float*)d_in[6];
    const float* bp  = (const float*)d_in[7];
    float* out = (float*)d_out;

    __half *p_qT, *p_kT, *p_v, *p_aoT, *p_SP, *p_wph;
    float *p_pmx, *p_inv;
    cudaGetSymbolAddress((void**)&p_qT,  g_qT);
    cudaGetSymbolAddress((void**)&p_kT,  g_kT);
    cudaGetSymbolAddress((void**)&p_v,   g_v);
    cudaGetSymbolAddress((void**)&p_aoT, g_aoT);
    cudaGetSymbolAddress((void**)&p_SP,  g_SP);
    cudaGetSymbolAddress((void**)&p_wph, g_wph);
    cudaGetSymbolAddress((void**)&p_pmx, g_pmx);
    cudaGetSymbolAddress((void**)&p_inv, g_inv);

    cudaFuncSetAttribute(tgemm<0, 3>, cudaFuncAttributeMaxDynamicSharedMemorySize,
                         SMEM_DYN);
    cudaFuncSetAttribute(tgemm<0, 2>, cudaFuncAttributeMaxDynamicSharedMemorySize,
                         SMEM_DYN);
    cudaFuncSetAttribute(tgemm<0, 0>, cudaFuncAttributeMaxDynamicSharedMemorySize,
                         SMEM_DYN);
    cudaFuncSetAttribute(qkv_gemm, cudaFuncAttributeMaxDynamicSharedMemorySize,
                         SMEM_DYN);
    cudaFuncSetAttribute(k_ln_fused, cudaFuncAttributeMaxDynamicSharedMemorySize,
                         SMEM_LN);

    const size_t sPC = (size_t)HWs * CH;
    const size_t sSS = (size_t)HWs * HWs;

    // 1..2: prep (weights + border), fused LN
    k_prep<<<1040, 256>>>(wq, wk, wv, wp);
    k_ln_fused<<<dim3(HWs / 32, NB), 256, SMEM_LN>>>(x, lnw, lnb);

    // 3: fused q/k/v convs
    qkv_gemm<<<dim3(384, 1, NB), 256, SMEM_DYN>>>();

    // 4: S[m,n] = scale * qT·kT -> fp16 logits + row-max partials (ncu slot)
    const float scale = 0.044194173824159216f;  // 512^-0.5
    tgemm<0, 3><<<dim3(32, 32, NB), 256, SMEM_DYN>>>(
        p_qT, p_kT, p_SP, nullptr, nullptr, p_pmx, nullptr,
        8, CH, CH, HWs, sPC, sPC, sSS, scale);

    // 5: single-pass softmax in place (unnormalized), 2 rows/block
    k_softmax1<<<dim3(HWs / 2, NB), 256>>>(p_SP);

    // 6: aoT[p][c] = (P_unnorm @ v) * inv[p]
    tgemm<0, 2><<<dim3(4, 32, NB), 256, SMEM_DYN>>>(
        p_SP, p_v, p_aoT, nullptr, nullptr, nullptr, p_inv,
        64, HWs, HWs, CH, sSS, sPC, sPC, 1.f);

    // 7: out[o,p] = x + wp*aoT + bp  (fp32)
    tgemm<0, 0><<<dim3(32, 4, NB), 256, SMEM_DYN>>>(
        p_wph, p_aoT, out, x, bp, nullptr, nullptr,
        8, CH, CH, HWs, 0, sPC, sPC, 1.f);
}

// round 16
// speedup vs baseline: 1.0795x; 1.0795x over previous
#include <cuda_runtime.h>
#include <cuda_fp16.h>
#include <cstdint>

// ===========================================================================
// AttnBlock via mma.sync m16n8k16 fp16 (fp32 accum), sm_100-safe.
// Round 16 (FINAL): exact revert to the measured optimum (R14, 1062.9us).
//   - 128x128 block, 8 warps of 32x64, BK=64, ST=2 (&1 staging), CP_WAIT(0)
//   - ldmatrix.x4 fragments, explicit double-buffering across ks-steps
//   - cp.async.ca for cross-tap hpT gathers, .cg for streams
//   - fused LN (1 read of x, transposed fp16 hpT), border-only zero
//   - fp16 logits + epilogue row-max partials; single-pass softmax (FMA exp),
//     unnormalized probs with 1/sum folded into the O-GEMM epilogue
//   - bias+residual fused into the proj GEMM epilogue
// History: tf32->fp16 (2847->1888), epilogue orientation (1579), fastexp+
// fused qkv (1378), ldmatrix (1192), BK=64 (1098), .ca+fusedLN (1073),
// R14 micro (1063).  R10/R13/R15 shape+pipeline variants all regressed.
// ===========================================================================

namespace {
constexpr int CH   = 512;
constexpr int NB   = 4;
constexpr int HWs  = 4096;
constexpr int PWs  = 66;
constexpr int PHWs = PWs * PWs;   // 4356

constexpr int BM = 128, BN = 128, BK = 64;
constexpr int RS = 72;                           // padded row stride (halfs)
constexpr int A_HALFS = BM * RS;                 // 9216
constexpr int A_BYTES = A_HALFS * 2;             // 18432
constexpr int STAGE_BYTES = 2 * A_BYTES;         // 36864
constexpr int SMEM_DYN = 2 * STAGE_BYTES;        // 73728
constexpr int SMEM_LN  = CH * 33 * 4;            // 67584
}

// ------------------------- scratch (device globals) ------------------------
__device__ float  g_inv[NB * HWs];                 // 1/rowsum of exp
__device__ float  g_pmx[(size_t)NB * HWs * 64];    // per-row 64-col max partials
__device__ __half g_hpT[(size_t)NB * PHWs * CH];   // padded LN out, channel-last
__device__ __half g_qT [(size_t)NB * HWs * CH];    // [p][c]
__device__ __half g_kT [(size_t)NB * HWs * CH];    // [p][c]
__device__ __half g_v  [(size_t)NB * CH * HWs];    // [c][p]
__device__ __half g_aoT[(size_t)NB * HWs * CH];    // [p][c]
__device__ __half g_SP [(size_t)NB * HWs * HWs];   // fp16 logits -> unnorm probs
__device__ __half g_wkt[(size_t)9 * CH * CH];      // [t][o][i] fp16
__device__ __half g_wvt[(size_t)9 * CH * CH];
__device__ __half g_wqh[(size_t)CH * CH];
__device__ __half g_wph[(size_t)CH * CH];

// ------------------------------ PTX helpers --------------------------------
#define CP16(sa, g) \
    asm volatile("cp.async.cg.shared.global [%0], [%1], 16;" :: "r"(sa), "l"(g))
#define CP16CA(sa, g) \
    asm volatile("cp.async.ca.shared.global [%0], [%1], 16;" :: "r"(sa), "l"(g))
#define CP_COMMIT() asm volatile("cp.async.commit_group;" ::: "memory")
#define CP_WAIT(n)  asm volatile("cp.async.wait_group %0;" :: "n"(n) : "memory")

__device__ __forceinline__ uint32_t smem_u32(const void* p) {
    uint32_t a;
    asm("{ .reg .u64 t; cvta.to.shared.u64 t, %1; cvt.u32.u64 %0, t; }"
        : "=r"(a) : "l"(p));
    return a;
}

#define MMA_F16(c, a, b) \
    asm volatile("mma.sync.aligned.m16n8k16.row.col.f32.f16.f16.f32 " \
        "{%0,%1,%2,%3}, {%4,%5,%6,%7}, {%8,%9}, {%0,%1,%2,%3};" \
        : "+f"((c)[0]), "+f"((c)[1]), "+f"((c)[2]), "+f"((c)[3]) \
        : "r"((a)[0]), "r"((a)[1]), "r"((a)[2]), "r"((a)[3]), \
          "r"((b)[0]), "r"((b)[1]))

#define LDSM_X4(r0, r1, r2, r3, addr) \
    asm volatile("ldmatrix.sync.aligned.m8n8.x4.shared.b16 {%0,%1,%2,%3}, [%4];" \
        : "=r"(r0), "=r"(r1), "=r"(r2), "=r"(r3) : "r"(addr))

// FMA-pipe exp (no MUFU): exp(x) = 2^n * e^t, |t| <= ln2/2.  rel err ~2.4e-6.
__device__ __forceinline__ float fexp(float x) {
    x = fmaxf(x, -80.f);
    float y  = x * 1.4426950408889634f;
    float fn = rintf(y);
    float t  = (y - fn) * 0.6931471805599453f;
    float p  = 8.3333333e-3f;
    p = fmaf(p, t, 4.1666667e-2f);
    p = fmaf(p, t, 1.6666667e-1f);
    p = fmaf(p, t, 0.5f);
    p = fmaf(p, t, 1.f);
    p = fmaf(p, t, 1.f);
    return p * __int_as_float(((int)fn + 127) << 23);
}

// ------------------------------- small kernels ------------------------------
// weight prep (blocks 0..1023) + hpT border zero (blocks 1024..1039)
__global__ void k_prep(const float* __restrict__ wq, const float* __restrict__ wk,
                       const float* __restrict__ wv, const float* __restrict__ wp) {
    if (blockIdx.x < 1024) {
        int g = blockIdx.x * 256 + threadIdx.x;
        g_wqh[g] = __float2half(wq[g]);
        g_wph[g] = __float2half(wp[g]);
        #pragma unroll
        for (int t = 0; t < 9; t++) {
            g_wkt[(size_t)t * CH * CH + g] = __float2half(wk[(size_t)g * 9 + t]);
            g_wvt[(size_t)t * CH * CH + g] = __float2half(wv[(size_t)g * 9 + t]);
        }
    } else {
        const int jb = blockIdx.x - 1024;          // 0..15
        for (int r = 0; r < 65; r++) {
            int j = jb * 65 + r;                   // 0..1039
            int b = j / 260, i = j % 260;
            int spo;
            if (i < 66)       spo = i;                      // row 0
            else if (i < 132) spo = 65 * PWs + (i - 66);    // row 65
            else if (i < 196) spo = (i - 131) * PWs;        // col 0
            else              spo = (i - 195) * PWs + 65;   // col 65
            ((uint32_t*)&g_hpT[((size_t)b * PHWs + spo) * CH])[threadIdx.x] = 0u;
        }
    }
}

// fused LayerNorm: one x read, stats in-tile, transposed fp16 write to hpT
__global__ void k_ln_fused(const float* __restrict__ x,
                           const float* __restrict__ lw,
                           const float* __restrict__ lb) {
    extern __shared__ float tile[];            // [CH][33]
    __shared__ float rs1[8][32], rs2[8][32];
    const int b = blockIdx.y;
    const int p0 = blockIdx.x * 32;
    const int lx = threadIdx.x & 31, ly = threadIdx.x >> 5;

    const float* xb = x + (size_t)b * CH * HWs + p0;
    float s = 0.f, s2 = 0.f;
    for (int c = ly; c < CH; c += 8) {
        float v = xb[(size_t)c * HWs + lx];
        tile[c * 33 + lx] = v;
        s += v; s2 += v * v;
    }
    rs1[ly][lx] = s; rs2[ly][lx] = s2;
    __syncthreads();
    if (ly == 0) {
        float a = 0.f, a2 = 0.f;
        #pragma unroll
        for (int j = 0; j < 8; j++) { a += rs1[j][lx]; a2 += rs2[j][lx]; }
        float mu = a * (1.f / CH);
        float var = a2 * (1.f / CH) - mu * mu;
        rs1[0][lx] = mu;
        rs2[0][lx] = rsqrtf(var + 1e-6f);
    }
    __syncthreads();

    const int c2 = threadIdx.x * 2;
    const float w0 = lw[c2], w1 = lw[c2 + 1];
    const float b0 = lb[c2], b1 = lb[c2 + 1];
    #pragma unroll 4
    for (int pp = 0; pp < 32; pp++) {
        const float mu = rs1[0][pp], r = rs2[0][pp];
        float v0 = (tile[c2 * 33 + pp] - mu) * r * w0 + b0;
        float v1 = (tile[(c2 + 1) * 33 + pp] - mu) * r * w1 + b1;
        int p = p0 + pp;
        int spo = ((p >> 6) + 1) * PWs + (p & 63) + 1;
        *(__half2*)&g_hpT[((size_t)b * PHWs + spo) * CH + c2] =
            __floats2half2_rn(v0, v1);
    }
}

// single-pass softmax, IN PLACE, 2 rows per block.  Row max from g_pmx.
// Writes UNNORMALIZED exp values; 1/sum goes to g_inv (applied in O-GEMM).
__global__ void k_softmax1(__half* __restrict__ SP) {
    const int b = blockIdx.y;
    __shared__ float red[8];
    const int tid = threadIdx.x;
    const int lane = tid & 31, wid = tid >> 5;

    #pragma unroll
    for (int rr = 0; rr < 2; rr++) {
        const int m = blockIdx.x * 2 + rr;
        __half* row = SP + ((size_t)b * HWs + m) * HWs;
        const float* pm = g_pmx + ((size_t)b * HWs + m) * 64;

        float mx = fmaxf(pm[lane], pm[lane + 32]);
        #pragma unroll
        for (int o = 16; o > 0; o >>= 1)
            mx = fmaxf(mx, __shfl_xor_sync(0xffffffffu, mx, o));

        float ls = 0.f;
        #pragma unroll
        for (int it = 0; it < 2; it++) {
            const int i = tid * 8 + it * 2048;
            uint4 u = *(const uint4*)&row[i];
            __half2* h = (__half2*)&u;
            #pragma unroll
            for (int q = 0; q < 4; q++) {
                float2 f = __half22float2(h[q]);
                f.x = fexp(f.x - mx);
                f.y = fexp(f.y - mx);
                ls += f.x + f.y;
                h[q] = __floats2half2_rn(f.x, f.y);
            }
            *(uint4*)&row[i] = u;
        }
        #pragma unroll
        for (int o = 16; o > 0; o >>= 1)
            ls += __shfl_xor_sync(0xffffffffu, ls, o);
        if (lane == 0) red[wid] = ls;
        __syncthreads();
        if (tid == 0) {
            float sum = 0.f;
            #pragma unroll
            for (int w = 0; w < 8; w++) sum += red[w];
            g_inv[b * HWs + m] = 1.f / sum;
        }
        if (rr == 0) __syncthreads();
    }
}

// ---------------------- fp16 mma.sync GEMM core (templated) -----------------
// Block 128x128, 8 warps of 32x64, BK=64, ST=2, fragment double-buffering.
// MODE 0: dense A(lda) / dense B(ldb)
// MODE 1: A = hpT gather (1 tap), B dense
// MODE 2: A = hpT gather (9 taps), B = weight slabs (+t*CH*CH)
// MODE 3: A = weight slabs,        B = hpT gather (9 taps)
// EPI 0: float C = alpha*acc (+bias[m]) (+resid)
// EPI 2: half  C = alpha*acc * (rowScale ? rowScale[m] : 1)
// EPI 3: half  C = alpha*acc, plus per-row 64-col max -> pmx
template <int MODE, int EPI>
__device__ __forceinline__ void gemm_core(
    const __half* __restrict__ A, const __half* __restrict__ B,
    void* __restrict__ Cv, const float* __restrict__ resid,
    const float* __restrict__ bias, float* __restrict__ pmx,
    const float* __restrict__ rowScale,
    int KT, int lda, int ldb, int ldc,
    float alpha, int mBase, int nBase) {
    extern __shared__ char dsm[];
    const int tid = threadIdx.x;
    const int lane = tid & 31;
    const int w  = tid >> 5;
    const int wm = (w & 3) * 32;
    const int wn = (w >> 2) * 64;
    const int g  = lane >> 2;
    const int t4 = lane & 3;

    // producer addressing: 4 A + 4 B chunks of 16B per thread per k-tile
    uint32_t aSm[4];
    uint32_t aOff[4], bOff[4];
    int q8[4];
    const uint32_t smBase = smem_u32(dsm);
    #pragma unroll
    for (int i = 0; i < 4; i++) {
        int chunk = tid + 256 * i;
        int r = chunk >> 3;
        q8[i] = (chunk & 7) * 8;
        aSm[i] = (uint32_t)(r * RS + q8[i]) * 2u;
        int pa = mBase + r, pb = nBase + r;
        if (MODE == 1 || MODE == 2)
            aOff[i] = (uint32_t)(((pa >> 6) + 1) * PWs + (pa & 63) + 1);
        else
            aOff[i] = (uint32_t)(pa * lda + q8[i]);
        if (MODE == 3)
            bOff[i] = (uint32_t)(((pb >> 6) + 1) * PWs + (pb & 63) + 1);
        else
            bOff[i] = (uint32_t)(pb * ldb + q8[i]);
    }

    // ldmatrix per-lane fragment bases (byte offsets within a stage)
    const uint32_t aFrag = smBase +
        (uint32_t)(((lane & 15) * RS + (lane >> 4) * 8) * 2) + (uint32_t)(wm * RS * 2);
    const uint32_t bFrag = smBase + (uint32_t)A_BYTES +
        (uint32_t)(((((lane & 7) + ((lane >> 4) << 3))) * RS + ((lane >> 3) & 1) * 8) * 2)
        + (uint32_t)(wn * RS * 2);

    float acc[2][8][4];
    #pragma unroll
    for (int mt = 0; mt < 2; mt++)
        #pragma unroll
        for (int nt = 0; nt < 8; nt++)
            #pragma unroll
            for (int e = 0; e < 4; e++) acc[mt][nt][e] = 0.f;

    auto issue = [&](int kt) {
        if (kt < KT) {
            const uint32_t sb = smBase + (uint32_t)((kt & 1) * STAGE_BYTES);
            const int kg = kt * BK;
            if (MODE == 0) {
                #pragma unroll
                for (int i = 0; i < 4; i++) {
                    CP16(sb + aSm[i], A + aOff[i] + kg);
                    CP16(sb + A_BYTES + aSm[i], B + bOff[i] + kg);
                }
            } else {
                int t, kc, off;
                if (MODE == 1) { t = 0; kc = kg; off = 0; }
                else {
                    t = kg >> 9; kc = kg & 511;
                    off = (t / 3 - 1) * PWs + (t % 3 - 1);
                }
                if (MODE == 1 || MODE == 2) {
                    const __half* Slab = B + ((size_t)t << 18);
                    #pragma unroll
                    for (int i = 0; i < 4; i++) {
                        CP16CA(sb + aSm[i],
                               A + ((size_t)(aOff[i] + off) << 9) + kc + q8[i]);
                        CP16(sb + A_BYTES + aSm[i],
                             (MODE == 1) ? (B + bOff[i] + kg) : (Slab + bOff[i] + kc));
                    }
                } else {  // MODE 3
                    const __half* Slab = A + ((size_t)t << 18);
                    #pragma unroll
                    for (int i = 0; i < 4; i++) {
                        CP16(sb + aSm[i], Slab + aOff[i] + kc);
                        CP16CA(sb + A_BYTES + aSm[i],
                               B + ((size_t)(bOff[i] + off) << 9) + kc + q8[i]);
                    }
                }
            }
            CP_COMMIT();
        }
    };

    issue(0);

    uint32_t a[2][2][4], b[2][8][2];   // double-buffered fragments
    for (int kt = 0; kt < KT; kt++) {
        CP_WAIT(0);
        __syncthreads();
        issue(kt + 1);

        const uint32_t soff = (uint32_t)((kt & 1) * STAGE_BYTES);
        // prime fragment buffer 0 (ks = 0)
        LDSM_X4(a[0][0][0], a[0][0][1], a[0][0][2], a[0][0][3], aFrag + soff);
        LDSM_X4(a[0][1][0], a[0][1][1], a[0][1][2], a[0][1][3],
                aFrag + soff + (uint32_t)(16 * RS * 2));
        #pragma unroll
        for (int np = 0; np < 4; np++)
            LDSM_X4(b[0][2 * np][0], b[0][2 * np][1],
                    b[0][2 * np + 1][0], b[0][2 * np + 1][1],
                    bFrag + soff + (uint32_t)(np * 16 * RS * 2));

        #pragma unroll
        for (int ks = 0; ks < 4; ks++) {
            const int cur = ks & 1, nxt = cur ^ 1;
            if (ks < 3) {
                const uint32_t ko2 = soff + (ks + 1) * 32;
                LDSM_X4(a[nxt][0][0], a[nxt][0][1], a[nxt][0][2], a[nxt][0][3],
                        aFrag + ko2);
                LDSM_X4(a[nxt][1][0], a[nxt][1][1], a[nxt][1][2], a[nxt][1][3],
                        aFrag + ko2 + (uint32_t)(16 * RS * 2));
                #pragma unroll
                for (int np = 0; np < 4; np++)
                    LDSM_X4(b[nxt][2 * np][0], b[nxt][2 * np][1],
                            b[nxt][2 * np + 1][0], b[nxt][2 * np + 1][1],
                            bFrag + ko2 + (uint32_t)(np * 16 * RS * 2));
            }
            #pragma unroll
            for (int mt = 0; mt < 2; mt++)
                #pragma unroll
                for (int nt = 0; nt < 8; nt++)
                    MMA_F16(acc[mt][nt], a[cur][mt], b[cur][nt]);
        }
    }

    if (EPI == 0) {
        float* C = (float*)Cv;
        #pragma unroll
        for (int mt = 0; mt < 2; mt++) {
            const int r0 = mBase + wm + mt * 16 + g;
            const int r1 = r0 + 8;
            const float bv0 = bias ? bias[r0] : 0.f;
            const float bv1 = bias ? bias[r1] : 0.f;
            #pragma unroll
            for (int nt = 0; nt < 8; nt++) {
                const int cc = nBase + wn + nt * 8 + 2 * t4;
                float2 o0, o1;
                o0.x = acc[mt][nt][0] * alpha + bv0;
                o0.y = acc[mt][nt][1] * alpha + bv0;
                o1.x = acc[mt][nt][2] * alpha + bv1;
                o1.y = acc[mt][nt][3] * alpha + bv1;
                if (resid) {
                    float2 q0 = *(const float2*)&resid[(size_t)r0 * ldc + cc];
                    float2 q1 = *(const float2*)&resid[(size_t)r1 * ldc + cc];
                    o0.x += q0.x; o0.y += q0.y;
                    o1.x += q1.x; o1.y += q1.y;
                }
                *(float2*)&C[(size_t)r0 * ldc + cc] = o0;
                *(float2*)&C[(size_t)r1 * ldc + cc] = o1;
            }
        }
    } else if (EPI == 2) {
        __half* C = (__half*)Cv;
        #pragma unroll
        for (int mt = 0; mt < 2; mt++) {
            const int r0 = mBase + wm + mt * 16 + g;
            const int r1 = r0 + 8;
            const float s0 = rowScale ? alpha * rowScale[r0] : alpha;
            const float s1 = rowScale ? alpha * rowScale[r1] : alpha;
            #pragma unroll
            for (int nt = 0; nt < 8; nt++) {
                const int cc = nBase + wn + nt * 8 + 2 * t4;
                __half2 h0 = __floats2half2_rn(acc[mt][nt][0] * s0,
                                               acc[mt][nt][1] * s0);
                __half2 h1 = __floats2half2_rn(acc[mt][nt][2] * s1,
                                               acc[mt][nt][3] * s1);
                *(__half2*)&C[(size_t)r0 * ldc + cc] = h0;
                *(__half2*)&C[(size_t)r1 * ldc + cc] = h1;
            }
        }
    } else {  // EPI 3: fp16 store + per-row 64-col max partials
        __half* C = (__half*)Cv;
        const int pblk = (nBase + wn) >> 6;
        #pragma unroll
        for (int mt = 0; mt < 2; mt++) {
            const int r0 = mBase + wm + mt * 16 + g;
            const int r1 = r0 + 8;
            float m0 = -1e30f, m1 = -1e30f;
            #pragma unroll
            for (int nt = 0; nt < 8; nt++) {
                const int cc = nBase + wn + nt * 8 + 2 * t4;
                float a0 = acc[mt][nt][0] * alpha, a1 = acc[mt][nt][1] * alpha;
                float a2 = acc[mt][nt][2] * alpha, a3 = acc[mt][nt][3] * alpha;
                m0 = fmaxf(m0, fmaxf(a0, a1));
                m1 = fmaxf(m1, fmaxf(a2, a3));
                *(__half2*)&C[(size_t)r0 * ldc + cc] = __floats2half2_rn(a0, a1);
                *(__half2*)&C[(size_t)r1 * ldc + cc] = __floats2half2_rn(a2, a3);
            }
            m0 = fmaxf(m0, __shfl_xor_sync(0xffffffffu, m0, 1));
            m0 = fmaxf(m0, __shfl_xor_sync(0xffffffffu, m0, 2));
            m1 = fmaxf(m1, __shfl_xor_sync(0xffffffffu, m1, 1));
            m1 = fmaxf(m1, __shfl_xor_sync(0xffffffffu, m1, 2));
            if (t4 == 0) {
                pmx[(size_t)r0 * 64 + pblk] = m0;
                pmx[(size_t)r1 * 64 + pblk] = m1;
            }
        }
    }
}

// generic GEMM wrapper (S, O, proj) — templated
template <int MODE, int EPI>
__global__ void __launch_bounds__(256, 2)
tgemm(const __half* __restrict__ A, const __half* __restrict__ B,
      void* __restrict__ Cv, const float* __restrict__ resid,
      const float* __restrict__ bias, float* __restrict__ pmx,
      const float* __restrict__ rowScale,
      int KT, int lda, int ldb, int ldc,
      size_t sA, size_t sB, size_t sC, float alpha) {
    const int z = blockIdx.z;
    gemm_core<MODE, EPI>(A + z * sA, B + z * sB,
              (EPI == 0) ? (void*)((float*)Cv + z * sC)
                         : (void*)((__half*)Cv + z * sC),
              resid ? resid + z * sC : nullptr, bias,
              pmx ? pmx + (size_t)z * HWs * 64 : nullptr,
              rowScale ? rowScale + (size_t)z * HWs : nullptr,
              KT, lda, ldb, ldc, alpha,
              blockIdx.y * BM, blockIdx.x * BN);
}

// fused q/k/v conv launch: 384 blocks per batch; heavy v/k first, cheap q last
__global__ void __launch_bounds__(256, 2)
qkv_gemm() {
    const int z = blockIdx.z;
    const size_t sHP = (size_t)PHWs * CH;
    const size_t sPC = (size_t)HWs * CH;
    const __half* hp = g_hpT + z * sHP;
    const int bx = blockIdx.x;
    if (bx < 128) {            // v: M=c, N=p, 9 taps
        gemm_core<3, 2>(g_wvt, hp, g_v + z * sPC, nullptr, nullptr, nullptr, nullptr,
                  72, CH, CH, HWs, 1.f, (bx >> 5) * BM, (bx & 31) * BN);
    } else if (bx < 256) {     // k: M=p, N=c, 9 taps
        const int j = bx - 128;
        gemm_core<2, 2>(hp, g_wkt, g_kT + z * sPC, nullptr, nullptr, nullptr, nullptr,
                  72, CH, CH, CH, 1.f, (j >> 2) * BM, (j & 3) * BN);
    } else {                   // q: M=p, N=c, 1 tap (cheap tail filler)
        const int j = bx - 256;
        gemm_core<1, 2>(hp, g_wqh, g_qT + z * sPC, nullptr, nullptr, nullptr, nullptr,
                  8, CH, CH, CH, 1.f, (j >> 2) * BM, (j & 3) * BN);
    }
}

// ------------------------------- launcher -----------------------------------
extern "C" void kernel_launch(void* const* d_in, const int* in_sizes, int n_in,
                              void* d_out, int out_size) {
    const float* x   = (const float*)d_in[0];
    const float* lnw = (const float*)d_in[1];
    const float* lnb = (const float*)d_in[2];
    const float* wq  = (const float*)d_in[3];
    const float* wk  = (const float*)d_in[4];
    const float* wv  = (const float*)d_in[5];
    const float* wp  = (const float*)d_in[6];
    const float* bp  = (const float*)d_in[7];
    float* out = (float*)d_out;

    __half *p_qT, *p_kT, *p_v, *p_aoT, *p_SP, *p_wph;
    float *p_pmx, *p_inv;
    cudaGetSymbolAddress((void**)&p_qT,  g_qT);
    cudaGetSymbolAddress((void**)&p_kT,  g_kT);
    cudaGetSymbolAddress((void**)&p_v,   g_v);
    cudaGetSymbolAddress((void**)&p_aoT, g_aoT);
    cudaGetSymbolAddress((void**)&p_SP,  g_SP);
    cudaGetSymbolAddress((void**)&p_wph, g_wph);
    cudaGetSymbolAddress((void**)&p_pmx, g_pmx);
    cudaGetSymbolAddress((void**)&p_inv, g_inv);

    cudaFuncSetAttribute(tgemm<0, 3>, cudaFuncAttributeMaxDynamicSharedMemorySize,
                         SMEM_DYN);
    cudaFuncSetAttribute(tgemm<0, 2>, cudaFuncAttributeMaxDynamicSharedMemorySize,
                         SMEM_DYN);
    cudaFuncSetAttribute(tgemm<0, 0>, cudaFuncAttributeMaxDynamicSharedMemorySize,
                         SMEM_DYN);
    cudaFuncSetAttribute(qkv_gemm, cudaFuncAttributeMaxDynamicSharedMemorySize,
                         SMEM_DYN);
    cudaFuncSetAttribute(k_ln_fused, cudaFuncAttributeMaxDynamicSharedMemorySize,
                         SMEM_LN);

    const size_t sPC = (size_t)HWs * CH;
    const size_t sSS = (size_t)HWs * HWs;

    // 1..2: prep (weights + border), fused LN
    k_prep<<<1040, 256>>>(wq, wk, wv, wp);
    k_ln_fused<<<dim3(HWs / 32, NB), 256, SMEM_LN>>>(x, lnw, lnb);

    // 3: fused q/k/v convs
    qkv_gemm<<<dim3(384, 1, NB), 256, SMEM_DYN>>>();

    // 4: S[m,n] = scale * qT·kT -> fp16 logits + row-max partials
    const float scale = 0.044194173824159216f;  // 512^-0.5
    tgemm<0, 3><<<dim3(32, 32, NB), 256, SMEM_DYN>>>(
        p_qT, p_kT, p_SP, nullptr, nullptr, p_pmx, nullptr,
        8, CH, CH, HWs, sPC, sPC, sSS, scale);

    // 5: single-pass softmax in place (unnormalized), 2 rows/block
    k_softmax1<<<dim3(HWs / 2, NB), 256>>>(p_SP);

    // 6: aoT[p][c] = (P_unnorm @ v) * inv[p]
    tgemm<0, 2><<<dim3(4, 32, NB), 256, SMEM_DYN>>>(
        p_SP, p_v, p_aoT, nullptr, nullptr, nullptr, p_inv,
        64, HWs, HWs, CH, sSS, sPC, sPC, 1.f);

    // 7: out[o,p] = x + wp*aoT + bp  (fp32)
    tgemm<0, 0><<<dim3(32, 4, NB), 256, SMEM_DYN>>>(
        p_wph, p_aoT, out, x, bp, nullptr, nullptr,
        8, CH, CH, HWs, 0, sPC, sPC, 1.f);
}

// round 17
// speedup vs baseline: 1.1098x; 1.0281x over previous
#include <cuda_runtime.h>
#include <cuda_fp16.h>
#include <cstdint>

// ===========================================================================
// AttnBlock via mma.sync m16n8k16 fp16 (fp32 accum), sm_100-safe.
// Round 17: algebraic weight folds on top of the R14/R16 optimum.
//   q-fold: wqk[t][i][j] = sum_c wq[c,i] wk[c,j,t]  =>  S = hT . (wqk (*) h)^T
//           (q-conv and qT eliminated; S-GEMM gathers hpT directly)
//   p-fold: wvp[t][o][j] = sum_c wp[o,c] wv[c,j,t]  =>  out = (wvp(*)h).P~^T.inv
//           (proj GEMM and aoT eliminated; O-GEMM writes out directly with
//            per-column inv, bias, residual)
// GEMM core unchanged from the measured optimum (128x128, 32x64 warps, BK=64,
// ST=2, CP_WAIT(0), ldmatrix + fragment double-buffer, .ca gathers).
// ===========================================================================

namespace {
constexpr int CH   = 512;
constexpr int NB   = 4;
constexpr int HWs  = 4096;
constexpr int PWs  = 66;
constexpr int PHWs = PWs * PWs;   // 4356

constexpr int BM = 128, BN = 128, BK = 64;
constexpr int RS = 72;                           // padded row stride (halfs)
constexpr int A_HALFS = BM * RS;                 // 9216
constexpr int A_BYTES = A_HALFS * 2;             // 18432
constexpr int STAGE_BYTES = 2 * A_BYTES;         // 36864
constexpr int SMEM_DYN = 2 * STAGE_BYTES;        // 73728
constexpr int SMEM_LN  = CH * 33 * 4;            // 67584
}

// ------------------------- scratch (device globals) ------------------------
__device__ float  g_inv[NB * HWs];                 // 1/rowsum of exp
__device__ float  g_pmx[(size_t)NB * HWs * 64];    // per-row 64-col max partials
__device__ __half g_hpT[(size_t)NB * PHWs * CH];   // padded LN out, channel-last
__device__ __half g_kT [(size_t)NB * HWs * CH];    // k' = wqk (*) h   [p][i]
__device__ __half g_v  [(size_t)NB * CH * HWs];    // v' = wvp (*) h   [o][p]
__device__ __half g_SP [(size_t)NB * HWs * HWs];   // fp16 logits -> unnorm probs
__device__ __half g_wqT [(size_t)CH * CH];         // wq^T  [i][c]
__device__ __half g_wktT[(size_t)9 * CH * CH];     // wk^T  [t][j][c]
__device__ __half g_wvtT[(size_t)9 * CH * CH];     // wv^T  [t][j][c]
__device__ __half g_wph [(size_t)CH * CH];         // wp    [o][c]
__device__ __half g_wqk [(size_t)9 * CH * CH];     // folded [t][i][j]
__device__ __half g_wvp [(size_t)9 * CH * CH];     // folded [t][o][j]

// ------------------------------ PTX helpers --------------------------------
#define CP16(sa, g) \
    asm volatile("cp.async.cg.shared.global [%0], [%1], 16;" :: "r"(sa), "l"(g))
#define CP16CA(sa, g) \
    asm volatile("cp.async.ca.shared.global [%0], [%1], 16;" :: "r"(sa), "l"(g))
#define CP_COMMIT() asm volatile("cp.async.commit_group;" ::: "memory")
#define CP_WAIT(n)  asm volatile("cp.async.wait_group %0;" :: "n"(n) : "memory")

__device__ __forceinline__ uint32_t smem_u32(const void* p) {
    uint32_t a;
    asm("{ .reg .u64 t; cvta.to.shared.u64 t, %1; cvt.u32.u64 %0, t; }"
        : "=r"(a) : "l"(p));
    return a;
}

#define MMA_F16(c, a, b) \
    asm volatile("mma.sync.aligned.m16n8k16.row.col.f32.f16.f16.f32 " \
        "{%0,%1,%2,%3}, {%4,%5,%6,%7}, {%8,%9}, {%0,%1,%2,%3};" \
        : "+f"((c)[0]), "+f"((c)[1]), "+f"((c)[2]), "+f"((c)[3]) \
        : "r"((a)[0]), "r"((a)[1]), "r"((a)[2]), "r"((a)[3]), \
          "r"((b)[0]), "r"((b)[1]))

#define LDSM_X4(r0, r1, r2, r3, addr) \
    asm volatile("ldmatrix.sync.aligned.m8n8.x4.shared.b16 {%0,%1,%2,%3}, [%4];" \
        : "=r"(r0), "=r"(r1), "=r"(r2), "=r"(r3) : "r"(addr))

// FMA-pipe exp (no MUFU): exp(x) = 2^n * e^t, |t| <= ln2/2.  rel err ~2.4e-6.
__device__ __forceinline__ float fexp(float x) {
    x = fmaxf(x, -80.f);
    float y  = x * 1.4426950408889634f;
    float fn = rintf(y);
    float t  = (y - fn) * 0.6931471805599453f;
    float p  = 8.3333333e-3f;
    p = fmaf(p, t, 4.1666667e-2f);
    p = fmaf(p, t, 1.6666667e-1f);
    p = fmaf(p, t, 0.5f);
    p = fmaf(p, t, 1.f);
    p = fmaf(p, t, 1.f);
    return p * __int_as_float(((int)fn + 127) << 23);
}

// ------------------------------- small kernels ------------------------------
// weight transposes (smem-tiled, blocks 0..255) + hpT border zero (256..271)
__global__ void k_prep(const float* __restrict__ wq, const float* __restrict__ wk,
                       const float* __restrict__ wv, const float* __restrict__ wp) {
    if (blockIdx.x < 256) {
        __shared__ float ts[32][33];
        const int c0 = (blockIdx.x >> 4) * 32;   // summation channel c
        const int i0 = (blockIdx.x & 15) * 32;   // inner channel i/j (or wp col)
        const int lx = threadIdx.x & 31, ly = threadIdx.x >> 5;

        // wp: direct copy [o][c]
        #pragma unroll
        for (int r = 0; r < 32; r += 8) {
            size_t idx = (size_t)(c0 + ly + r) * CH + i0 + lx;
            g_wph[idx] = __float2half(wp[idx]);
        }
        // wq transpose -> wqT[i][c]
        #pragma unroll
        for (int r = 0; r < 32; r += 8)
            ts[ly + r][lx] = wq[(size_t)(c0 + ly + r) * CH + i0 + lx];
        __syncthreads();
        #pragma unroll
        for (int r = 0; r < 32; r += 8)
            g_wqT[(size_t)(i0 + ly + r) * CH + c0 + lx] =
                __float2half(ts[lx][ly + r]);
        // wk/wv per-tap transposes -> [t][j][c]
        for (int t = 0; t < 9; t++) {
            __syncthreads();
            #pragma unroll
            for (int r = 0; r < 32; r += 8)
                ts[ly + r][lx] =
                    wk[((size_t)(c0 + ly + r) * CH + i0 + lx) * 9 + t];
            __syncthreads();
            #pragma unroll
            for (int r = 0; r < 32; r += 8)
                g_wktT[(size_t)t * CH * CH + (size_t)(i0 + ly + r) * CH + c0 + lx] =
                    __float2half(ts[lx][ly + r]);
        }
        for (int t = 0; t < 9; t++) {
            __syncthreads();
            #pragma unroll
            for (int r = 0; r < 32; r += 8)
                ts[ly + r][lx] =
                    wv[((size_t)(c0 + ly + r) * CH + i0 + lx) * 9 + t];
            __syncthreads();
            #pragma unroll
            for (int r = 0; r < 32; r += 8)
                g_wvtT[(size_t)t * CH * CH + (size_t)(i0 + ly + r) * CH + c0 + lx] =
                    __float2half(ts[lx][ly + r]);
        }
    } else {
        const int jb = blockIdx.x - 256;           // 0..15
        for (int r = 0; r < 65; r++) {
            int j = jb * 65 + r;                   // 0..1039
            int b = j / 260, i = j % 260;
            int spo;
            if (i < 66)       spo = i;                      // row 0
            else if (i < 132) spo = 65 * PWs + (i - 66);    // row 65
            else if (i < 196) spo = (i - 131) * PWs;        // col 0
            else              spo = (i - 195) * PWs + 65;   // col 65
            ((uint32_t*)&g_hpT[((size_t)b * PHWs + spo) * CH])[threadIdx.x] = 0u;
        }
    }
}

// fused LayerNorm: one x read, stats in-tile, transposed fp16 write to hpT
__global__ void k_ln_fused(const float* __restrict__ x,
                           const float* __restrict__ lw,
                           const float* __restrict__ lb) {
    extern __shared__ float tile[];            // [CH][33]
    __shared__ float rs1[8][32], rs2[8][32];
    const int b = blockIdx.y;
    const int p0 = blockIdx.x * 32;
    const int lx = threadIdx.x & 31, ly = threadIdx.x >> 5;

    const float* xb = x + (size_t)b * CH * HWs + p0;
    float s = 0.f, s2 = 0.f;
    for (int c = ly; c < CH; c += 8) {
        float v = xb[(size_t)c * HWs + lx];
        tile[c * 33 + lx] = v;
        s += v; s2 += v * v;
    }
    rs1[ly][lx] = s; rs2[ly][lx] = s2;
    __syncthreads();
    if (ly == 0) {
        float a = 0.f, a2 = 0.f;
        #pragma unroll
        for (int j = 0; j < 8; j++) { a += rs1[j][lx]; a2 += rs2[j][lx]; }
        float mu = a * (1.f / CH);
        float var = a2 * (1.f / CH) - mu * mu;
        rs1[0][lx] = mu;
        rs2[0][lx] = rsqrtf(var + 1e-6f);
    }
    __syncthreads();

    const int c2 = threadIdx.x * 2;
    const float w0 = lw[c2], w1 = lw[c2 + 1];
    const float b0 = lb[c2], b1 = lb[c2 + 1];
    #pragma unroll 4
    for (int pp = 0; pp < 32; pp++) {
        const float mu = rs1[0][pp], r = rs2[0][pp];
        float v0 = (tile[c2 * 33 + pp] - mu) * r * w0 + b0;
        float v1 = (tile[(c2 + 1) * 33 + pp] - mu) * r * w1 + b1;
        int p = p0 + pp;
        int spo = ((p >> 6) + 1) * PWs + (p & 63) + 1;
        *(__half2*)&g_hpT[((size_t)b * PHWs + spo) * CH + c2] =
            __floats2half2_rn(v0, v1);
    }
}

// single-pass softmax, IN PLACE, 2 rows per block.  Row max from g_pmx.
// Writes UNNORMALIZED exp values; 1/sum goes to g_inv (applied in O-GEMM).
__global__ void k_softmax1(__half* __restrict__ SP) {
    const int b = blockIdx.y;
    __shared__ float red[8];
    const int tid = threadIdx.x;
    const int lane = tid & 31, wid = tid >> 5;

    #pragma unroll
    for (int rr = 0; rr < 2; rr++) {
        const int m = blockIdx.x * 2 + rr;
        __half* row = SP + ((size_t)b * HWs + m) * HWs;
        const float* pm = g_pmx + ((size_t)b * HWs + m) * 64;

        float mx = fmaxf(pm[lane], pm[lane + 32]);
        #pragma unroll
        for (int o = 16; o > 0; o >>= 1)
            mx = fmaxf(mx, __shfl_xor_sync(0xffffffffu, mx, o));

        float ls = 0.f;
        #pragma unroll
        for (int it = 0; it < 2; it++) {
            const int i = tid * 8 + it * 2048;
            uint4 u = *(const uint4*)&row[i];
            __half2* h = (__half2*)&u;
            #pragma unroll
            for (int q = 0; q < 4; q++) {
                float2 f = __half22float2(h[q]);
                f.x = fexp(f.x - mx);
                f.y = fexp(f.y - mx);
                ls += f.x + f.y;
                h[q] = __floats2half2_rn(f.x, f.y);
            }
            *(uint4*)&row[i] = u;
        }
        #pragma unroll
        for (int o = 16; o > 0; o >>= 1)
            ls += __shfl_xor_sync(0xffffffffu, ls, o);
        if (lane == 0) red[wid] = ls;
        __syncthreads();
        if (tid == 0) {
            float sum = 0.f;
            #pragma unroll
            for (int w = 0; w < 8; w++) sum += red[w];
            g_inv[b * HWs + m] = 1.f / sum;
        }
        if (rr == 0) __syncthreads();
    }
}

// ---------------------- fp16 mma.sync GEMM core (templated) -----------------
// Block 128x128, 8 warps of 32x64, BK=64, ST=2, fragment double-buffering.
// MODE 0: dense A(lda) / dense B(ldb)
// MODE 1: A = hpT gather (1 tap), B dense
// MODE 2: A = hpT gather (9 taps), B = weight slabs (+t*CH*CH)
// MODE 3: A = weight slabs,        B = hpT gather (9 taps)
// EPI 2: half  C = alpha*acc
// EPI 3: half  C = alpha*acc, plus per-row 64-col max -> pmx
// EPI 4: float C = acc*colScale[n] + bias[m] + resid[m*ldc+n]
template <int MODE, int EPI>
__device__ __forceinline__ void gemm_core(
    const __half* __restrict__ A, const __half* __restrict__ B,
    void* __restrict__ Cv, const float* __restrict__ resid,
    const float* __restrict__ bias, float* __restrict__ pmx,
    const float* __restrict__ colScale,
    int KT, int lda, int ldb, int ldc,
    float alpha, int mBase, int nBase) {
    extern __shared__ char dsm[];
    const int tid = threadIdx.x;
    const int lane = tid & 31;
    const int w  = tid >> 5;
    const int wm = (w & 3) * 32;
    const int wn = (w >> 2) * 64;
    const int g  = lane >> 2;
    const int t4 = lane & 3;

    // producer addressing: 4 A + 4 B chunks of 16B per thread per k-tile
    uint32_t aSm[4];
    uint32_t aOff[4], bOff[4];
    int q8[4];
    const uint32_t smBase = smem_u32(dsm);
    #pragma unroll
    for (int i = 0; i < 4; i++) {
        int chunk = tid + 256 * i;
        int r = chunk >> 3;
        q8[i] = (chunk & 7) * 8;
        aSm[i] = (uint32_t)(r * RS + q8[i]) * 2u;
        int pa = mBase + r, pb = nBase + r;
        if (MODE == 1 || MODE == 2)
            aOff[i] = (uint32_t)(((pa >> 6) + 1) * PWs + (pa & 63) + 1);
        else
            aOff[i] = (uint32_t)(pa * lda + q8[i]);
        if (MODE == 3)
            bOff[i] = (uint32_t)(((pb >> 6) + 1) * PWs + (pb & 63) + 1);
        else
            bOff[i] = (uint32_t)(pb * ldb + q8[i]);
    }

    // ldmatrix per-lane fragment bases (byte offsets within a stage)
    const uint32_t aFrag = smBase +
        (uint32_t)(((lane & 15) * RS + (lane >> 4) * 8) * 2) + (uint32_t)(wm * RS * 2);
    const uint32_t bFrag = smBase + (uint32_t)A_BYTES +
        (uint32_t)(((((lane & 7) + ((lane >> 4) << 3))) * RS + ((lane >> 3) & 1) * 8) * 2)
        + (uint32_t)(wn * RS * 2);

    float acc[2][8][4];
    #pragma unroll
    for (int mt = 0; mt < 2; mt++)
        #pragma unroll
        for (int nt = 0; nt < 8; nt++)
            #pragma unroll
            for (int e = 0; e < 4; e++) acc[mt][nt][e] = 0.f;

    auto issue = [&](int kt) {
        if (kt < KT) {
            const uint32_t sb = smBase + (uint32_t)((kt & 1) * STAGE_BYTES);
            const int kg = kt * BK;
            if (MODE == 0) {
                #pragma unroll
                for (int i = 0; i < 4; i++) {
                    CP16(sb + aSm[i], A + aOff[i] + kg);
                    CP16(sb + A_BYTES + aSm[i], B + bOff[i] + kg);
                }
            } else {
                int t, kc, off;
                if (MODE == 1) { t = 0; kc = kg; off = 0; }
                else {
                    t = kg >> 9; kc = kg & 511;
                    off = (t / 3 - 1) * PWs + (t % 3 - 1);
                }
                if (MODE == 1 || MODE == 2) {
                    const __half* Slab = B + ((size_t)t << 18);
                    #pragma unroll
                    for (int i = 0; i < 4; i++) {
                        CP16CA(sb + aSm[i],
                               A + ((size_t)(aOff[i] + off) << 9) + kc + q8[i]);
                        CP16(sb + A_BYTES + aSm[i],
                             (MODE == 1) ? (B + bOff[i] + kg) : (Slab + bOff[i] + kc));
                    }
                } else {  // MODE 3
                    const __half* Slab = A + ((size_t)t << 18);
                    #pragma unroll
                    for (int i = 0; i < 4; i++) {
                        CP16(sb + aSm[i], Slab + aOff[i] + kc);
                        CP16CA(sb + A_BYTES + aSm[i],
                               B + ((size_t)(bOff[i] + off) << 9) + kc + q8[i]);
                    }
                }
            }
            CP_COMMIT();
        }
    };

    issue(0);

    uint32_t a[2][2][4], b[2][8][2];   // double-buffered fragments
    for (int kt = 0; kt < KT; kt++) {
        CP_WAIT(0);
        __syncthreads();
        issue(kt + 1);

        const uint32_t soff = (uint32_t)((kt & 1) * STAGE_BYTES);
        // prime fragment buffer 0 (ks = 0)
        LDSM_X4(a[0][0][0], a[0][0][1], a[0][0][2], a[0][0][3], aFrag + soff);
        LDSM_X4(a[0][1][0], a[0][1][1], a[0][1][2], a[0][1][3],
                aFrag + soff + (uint32_t)(16 * RS * 2));
        #pragma unroll
        for (int np = 0; np < 4; np++)
            LDSM_X4(b[0][2 * np][0], b[0][2 * np][1],
                    b[0][2 * np + 1][0], b[0][2 * np + 1][1],
                    bFrag + soff + (uint32_t)(np * 16 * RS * 2));

        #pragma unroll
        for (int ks = 0; ks < 4; ks++) {
            const int cur = ks & 1, nxt = cur ^ 1;
            if (ks < 3) {
                const uint32_t ko2 = soff + (ks + 1) * 32;
                LDSM_X4(a[nxt][0][0], a[nxt][0][1], a[nxt][0][2], a[nxt][0][3],
                        aFrag + ko2);
                LDSM_X4(a[nxt][1][0], a[nxt][1][1], a[nxt][1][2], a[nxt][1][3],
                        aFrag + ko2 + (uint32_t)(16 * RS * 2));
                #pragma unroll
                for (int np = 0; np < 4; np++)
                    LDSM_X4(b[nxt][2 * np][0], b[nxt][2 * np][1],
                            b[nxt][2 * np + 1][0], b[nxt][2 * np + 1][1],
                            bFrag + ko2 + (uint32_t)(np * 16 * RS * 2));
            }
            #pragma unroll
            for (int mt = 0; mt < 2; mt++)
                #pragma unroll
                for (int nt = 0; nt < 8; nt++)
                    MMA_F16(acc[mt][nt], a[cur][mt], b[cur][nt]);
        }
    }

    if (EPI == 4) {
        float* C = (float*)Cv;
        #pragma unroll
        for (int mt = 0; mt < 2; mt++) {
            const int r0 = mBase + wm + mt * 16 + g;
            const int r1 = r0 + 8;
            const float bv0 = bias[r0];
            const float bv1 = bias[r1];
            #pragma unroll
            for (int nt = 0; nt < 8; nt++) {
                const int cc = nBase + wn + nt * 8 + 2 * t4;
                float2 iv = *(const float2*)&colScale[cc];
                float2 q0 = *(const float2*)&resid[(size_t)r0 * ldc + cc];
                float2 q1 = *(const float2*)&resid[(size_t)r1 * ldc + cc];
                float2 o0, o1;
                o0.x = fmaf(acc[mt][nt][0], iv.x, bv0 + q0.x);
                o0.y = fmaf(acc[mt][nt][1], iv.y, bv0 + q0.y);
                o1.x = fmaf(acc[mt][nt][2], iv.x, bv1 + q1.x);
                o1.y = fmaf(acc[mt][nt][3], iv.y, bv1 + q1.y);
                *(float2*)&C[(size_t)r0 * ldc + cc] = o0;
                *(float2*)&C[(size_t)r1 * ldc + cc] = o1;
            }
        }
    } else if (EPI == 2) {
        __half* C = (__half*)Cv;
        #pragma unroll
        for (int mt = 0; mt < 2; mt++) {
            const int r0 = mBase + wm + mt * 16 + g;
            const int r1 = r0 + 8;
            #pragma unroll
            for (int nt = 0; nt < 8; nt++) {
                const int cc = nBase + wn + nt * 8 + 2 * t4;
                __half2 h0 = __floats2half2_rn(acc[mt][nt][0] * alpha,
                                               acc[mt][nt][1] * alpha);
                __half2 h1 = __floats2half2_rn(acc[mt][nt][2] * alpha,
                                               acc[mt][nt][3] * alpha);
                *(__half2*)&C[(size_t)r0 * ldc + cc] = h0;
                *(__half2*)&C[(size_t)r1 * ldc + cc] = h1;
            }
        }
    } else {  // EPI 3: fp16 store + per-row 64-col max partials
        __half* C = (__half*)Cv;
        const int pblk = (nBase + wn) >> 6;
        #pragma unroll
        for (int mt = 0; mt < 2; mt++) {
            const int r0 = mBase + wm + mt * 16 + g;
            const int r1 = r0 + 8;
            float m0 = -1e30f, m1 = -1e30f;
            #pragma unroll
            for (int nt = 0; nt < 8; nt++) {
                const int cc = nBase + wn + nt * 8 + 2 * t4;
                float a0 = acc[mt][nt][0] * alpha, a1 = acc[mt][nt][1] * alpha;
                float a2 = acc[mt][nt][2] * alpha, a3 = acc[mt][nt][3] * alpha;
                m0 = fmaxf(m0, fmaxf(a0, a1));
                m1 = fmaxf(m1, fmaxf(a2, a3));
                *(__half2*)&C[(size_t)r0 * ldc + cc] = __floats2half2_rn(a0, a1);
                *(__half2*)&C[(size_t)r1 * ldc + cc] = __floats2half2_rn(a2, a3);
            }
            m0 = fmaxf(m0, __shfl_xor_sync(0xffffffffu, m0, 1));
            m0 = fmaxf(m0, __shfl_xor_sync(0xffffffffu, m0, 2));
            m1 = fmaxf(m1, __shfl_xor_sync(0xffffffffu, m1, 1));
            m1 = fmaxf(m1, __shfl_xor_sync(0xffffffffu, m1, 2));
            if (t4 == 0) {
                pmx[(size_t)r0 * 64 + pblk] = m0;
                pmx[(size_t)r1 * 64 + pblk] = m1;
            }
        }
    }
}

// generic GEMM wrapper (S, O') — templated, z-batched
template <int MODE, int EPI>
__global__ void __launch_bounds__(256, 2)
tgemm(const __half* __restrict__ A, const __half* __restrict__ B,
      void* __restrict__ Cv, const float* __restrict__ resid,
      const float* __restrict__ bias, float* __restrict__ pmx,
      const float* __restrict__ colScale,
      int KT, int lda, int ldb, int ldc,
      size_t sA, size_t sB, size_t sC, float alpha) {
    const int z = blockIdx.z;
    gemm_core<MODE, EPI>(A + z * sA, B + z * sB,
              (EPI == 4) ? (void*)((float*)Cv + z * sC)
                         : (void*)((__half*)Cv + z * sC),
              resid ? resid + z * sC : nullptr, bias,
              pmx ? pmx + (size_t)z * HWs * 64 : nullptr,
              colScale ? colScale + (size_t)z * HWs : nullptr,
              KT, lda, ldb, ldc, alpha,
              blockIdx.y * BM, blockIdx.x * BN);
}

// weight-fold GEMMs: wqk[t] = wqT . wktT[t]^T, wvp[t] = wph . wvtT[t]^T
// 288 blocks: 0..143 -> wqk (9 taps x 16 tiles), 144..287 -> wvp
__global__ void __launch_bounds__(256, 2)
fold_gemm() {
    int bx = blockIdx.x;
    if (bx < 144) {
        const int t = bx >> 4, j = bx & 15;
        gemm_core<0, 2>(g_wqT, g_wktT + (size_t)t * CH * CH,
                        g_wqk + (size_t)t * CH * CH,
                        nullptr, nullptr, nullptr, nullptr,
                        8, CH, CH, CH, 1.f, (j >> 2) * BM, (j & 3) * BN);
    } else {
        bx -= 144;
        const int t = bx >> 4, j = bx & 15;
        gemm_core<0, 2>(g_wph, g_wvtT + (size_t)t * CH * CH,
                        g_wvp + (size_t)t * CH * CH,
                        nullptr, nullptr, nullptr, nullptr,
                        8, CH, CH, CH, 1.f, (j >> 2) * BM, (j & 3) * BN);
    }
}

// fused k'/v' conv launch: 256 blocks per batch
__global__ void __launch_bounds__(256, 2)
kv_gemm() {
    const int z = blockIdx.z;
    const size_t sHP = (size_t)PHWs * CH;
    const size_t sPC = (size_t)HWs * CH;
    const __half* hp = g_hpT + z * sHP;
    const int bx = blockIdx.x;
    if (bx < 128) {            // v' = wvp (*) h : M=o, N=p, 9 taps
        gemm_core<3, 2>(g_wvp, hp, g_v + z * sPC, nullptr, nullptr, nullptr, nullptr,
                  72, CH, CH, HWs, 1.f, (bx >> 5) * BM, (bx & 31) * BN);
    } else {                   // k' = wqk (*) h : M=p, N=i, 9 taps
        const int j = bx - 128;
        gemm_core<2, 2>(hp, g_wqk, g_kT + z * sPC, nullptr, nullptr, nullptr, nullptr,
                  72, CH, CH, CH, 1.f, (j >> 2) * BM, (j & 3) * BN);
    }
}

// ------------------------------- launcher -----------------------------------
extern "C" void kernel_launch(void* const* d_in, const int* in_sizes, int n_in,
                              void* d_out, int out_size) {
    const float* x   = (const float*)d_in[0];
    const float* lnw = (const float*)d_in[1];
    const float* lnb = (const float*)d_in[2];
    const float* wq  = (const float*)d_in[3];
    const float* wk  = (const float*)d_in[4];
    const float* wv  = (const float*)d_in[5];
    const float* wp  = (const float*)d_in[6];
    const float* bp  = (const float*)d_in[7];
    float* out = (float*)d_out;

    __half *p_hpT, *p_kT, *p_v, *p_SP;
    float *p_pmx, *p_inv;
    cudaGetSymbolAddress((void**)&p_hpT, g_hpT);
    cudaGetSymbolAddress((void**)&p_kT,  g_kT);
    cudaGetSymbolAddress((void**)&p_v,   g_v);
    cudaGetSymbolAddress((void**)&p_SP,  g_SP);
    cudaGetSymbolAddress((void**)&p_pmx, g_pmx);
    cudaGetSymbolAddress((void**)&p_inv, g_inv);

    cudaFuncSetAttribute(tgemm<1, 3>, cudaFuncAttributeMaxDynamicSharedMemorySize,
                         SMEM_DYN);
    cudaFuncSetAttribute(tgemm<0, 4>, cudaFuncAttributeMaxDynamicSharedMemorySize,
                         SMEM_DYN);
    cudaFuncSetAttribute(fold_gemm, cudaFuncAttributeMaxDynamicSharedMemorySize,
                         SMEM_DYN);
    cudaFuncSetAttribute(kv_gemm, cudaFuncAttributeMaxDynamicSharedMemorySize,
                         SMEM_DYN);
    cudaFuncSetAttribute(k_ln_fused, cudaFuncAttributeMaxDynamicSharedMemorySize,
                         SMEM_LN);

    const size_t sHP = (size_t)PHWs * CH;
    const size_t sPC = (size_t)HWs * CH;
    const size_t sSS = (size_t)HWs * HWs;

    // 1: weight transposes + border zero
    k_prep<<<272, 256>>>(wq, wk, wv, wp);
    // 2: fused LN
    k_ln_fused<<<dim3(HWs / 32, NB), 256, SMEM_LN>>>(x, lnw, lnb);
    // 3: weight folds (wqk, wvp)
    fold_gemm<<<288, 256, SMEM_DYN>>>();
    // 4: k' and v' convs
    kv_gemm<<<dim3(256, 1, NB), 256, SMEM_DYN>>>();

    // 5: S[m,n] = scale * sum_i hT[m,i] k'T[n,i]  (A = hpT center gather)
    const float scale = 0.044194173824159216f;  // 512^-0.5
    tgemm<1, 3><<<dim3(32, 32, NB), 256, SMEM_DYN>>>(
        p_hpT, p_kT, p_SP, nullptr, nullptr, p_pmx, nullptr,
        8, CH, CH, HWs, sHP, sPC, sSS, scale);

    // 6: single-pass softmax in place (unnormalized), 2 rows/block
    k_softmax1<<<dim3(HWs / 2, NB), 256>>>(p_SP);

    // 7: out[o,p] = x + bp[o] + (sum_n v'[o,n] P~[p,n]) * inv[p]
    tgemm<0, 4><<<dim3(32, 4, NB), 256, SMEM_DYN>>>(
        p_v, p_SP, out, x, bp, nullptr, p_inv,
        64, HWs, HWs, HWs, sPC, sSS, sPC, 1.f);
}